// round 11
// baseline (speedup 1.0000x reference)
#include <cuda_runtime.h>
#include <cuda_fp16.h>
#include <stdint.h>
#include <math.h>

#define BATCH  4096
#define HIDDEN 1024
#define INPUT  512
#define NOUT   4096
#define KTOT   1536
#define BM     128
#define BN     128
#define BK     64
#define NCH    (KTOT / BK)          // 24
#define STAGES 3
#define TILE_B (BM * BK * 2)        // 16384 B
#define STAGE_B (2 * TILE_B)        // 32768 B
#define SMEM_B  (STAGES * STAGE_B)  // 98304 B -> 2 CTAs/SM

// ---------------- device scratch ----------------
__device__ __half g_lin[(size_t)BATCH * NOUT];   // fp16 lin scratch (32 MB, L2-resident)
__device__ __half g_A[(size_t)BATCH * KTOT];
__device__ __half g_B[(size_t)NOUT  * KTOT];
__device__ int    g_cnt[BATCH / BM];             // per-rowblock arrival counters (init 0)

// ---------------- helpers ----------------
__device__ __forceinline__ uint32_t smem_u32(const void* p) {
    uint32_t a;
    asm("{ .reg .u64 t; cvta.to.shared.u64 t, %1; cvt.u32.u64 %0, t; }" : "=r"(a) : "l"(p));
    return a;
}
#define CP16(dst, src) \
    asm volatile("cp.async.cg.shared.global [%0], [%1], 16;" :: "r"(dst), "l"(src) : "memory")
#define CP_COMMIT() asm volatile("cp.async.commit_group;" ::: "memory")
#define CP_WAIT(n)  asm volatile("cp.async.wait_group %0;" :: "n"(n) : "memory")

__device__ __forceinline__ void ldsm4(uint32_t* r, uint32_t addr) {
    asm volatile("ldmatrix.sync.aligned.m8n8.x4.shared.b16 {%0,%1,%2,%3}, [%4];"
                 : "=r"(r[0]), "=r"(r[1]), "=r"(r[2]), "=r"(r[3]) : "r"(addr));
}
__device__ __forceinline__ void mma16816(float* d, const uint32_t* a,
                                         uint32_t b0, uint32_t b1) {
    asm volatile("mma.sync.aligned.m16n8k16.row.col.f32.f16.f16.f32 "
                 "{%0,%1,%2,%3}, {%4,%5,%6,%7}, {%8,%9}, {%0,%1,%2,%3};"
                 : "+f"(d[0]), "+f"(d[1]), "+f"(d[2]), "+f"(d[3])
                 : "r"(a[0]), "r"(a[1]), "r"(a[2]), "r"(a[3]), "r"(b0), "r"(b1));
}
__device__ __forceinline__ uint32_t saddr(uint32_t tile, int row, int c) {
    return tile + (uint32_t)(row * 128) + ((uint32_t)((c ^ (row & 7)) << 4));
}
__device__ __forceinline__ float fsig(float x)  { return 1.0f / (1.0f + __expf(-x)); }
__device__ __forceinline__ float ftanh(float x) { return 1.0f - 2.0f / (1.0f + __expf(2.0f * x)); }
__device__ __forceinline__ float wredsum(float v) {
    #pragma unroll
    for (int o = 16; o > 0; o >>= 1) v += __shfl_xor_sync(0xffffffffu, v, o);
    return v;
}
__device__ __forceinline__ void h8_to_f(uint4 u, float* f) {
    const __half2* h = (const __half2*)&u;
    float2 a;
    a = __half22float2(h[0]); f[0] = a.x; f[1] = a.y;
    a = __half22float2(h[1]); f[2] = a.x; f[3] = a.y;
    a = __half22float2(h[2]); f[4] = a.x; f[5] = a.y;
    a = __half22float2(h[3]); f[6] = a.x; f[7] = a.y;
}

// ---------------- fp16 conversion: A = [x|h], B = [wih|whh] ----------------
__global__ __launch_bounds__(256)
void lnlstm_convert(const float* __restrict__ x,  const float* __restrict__ h,
                    const float* __restrict__ wi, const float* __restrict__ wh)
{
    const uint32_t idx = blockIdx.x * 256u + threadIdx.x;
    const uint32_t e0  = idx * 4u;
    const int row = e0 / KTOT;
    const int col = e0 % KTOT;
    const float* s1 = blockIdx.y ? wi : x;
    const float* s2 = blockIdx.y ? wh : h;
    float4 v;
    if (col < INPUT) v = *(const float4*)(s1 + (size_t)row * INPUT  + col);
    else             v = *(const float4*)(s2 + (size_t)row * HIDDEN + (col - INPUT));
    __half* dst = blockIdx.y ? g_B : g_A;
    __half2 p0 = __floats2half2_rn(v.x, v.y);
    __half2 p1 = __floats2half2_rn(v.z, v.w);
    uint2 u;
    u.x = *(uint32_t*)&p0;
    u.y = *(uint32_t*)&p1;
    *(uint2*)(dst + e0) = u;
}

// ---------------- fused GEMM + epilogue ----------------
// GEMM: CTA 128x128, 8 warps 2(M)x4(N), warp tile 64x32, 3 stages, 2 CTAs/SM.
// Last CTA of each row-block runs the LN/gate/cell epilogue for its 128 rows.
__global__ void __launch_bounds__(256, 2)
lnlstm_fused(const float* __restrict__ cin,
             const float* __restrict__ lnw_h, const float* __restrict__ lnb_h,
             const float* __restrict__ lnw_c, const float* __restrict__ lnb_c,
             float* __restrict__ h_out, float* __restrict__ c_out)
{
    extern __shared__ char smem[];
    const uint32_t sb = smem_u32(smem);
    const int tid  = threadIdx.x;
    const int wid  = tid >> 5;
    const int lane = tid & 31;
    const int m0 = blockIdx.y * BM;
    const int n0 = blockIdx.x * BN;

    // ======== GEMM phase ========
    const int trow = tid >> 1;
    const int tc0  = (tid & 1) * 4;
    const __half* gA = g_A + (size_t)(m0 + trow) * KTOT + tc0 * 8;
    const __half* gB = g_B + (size_t)(n0 + trow) * KTOT + tc0 * 8;
    uint32_t dofs[4];
    #pragma unroll
    for (int c = 0; c < 4; ++c)
        dofs[c] = (uint32_t)(trow * 128) + ((uint32_t)(((tc0 + c) ^ (trow & 7)) << 4));

    const int sub = lane >> 3, r8 = lane & 7;
    const int rA  = (wid >> 2) * 64 + (sub & 1) * 8 + r8;
    const int cA  = sub >> 1;
    const int rB  = (wid & 3) * 32 + (sub >> 1) * 8 + r8;
    const int cB  = sub & 1;

    float acc[4][4][4];
    #pragma unroll
    for (int i = 0; i < 4; ++i)
        #pragma unroll
        for (int j = 0; j < 4; ++j)
            #pragma unroll
            for (int q = 0; q < 4; ++q) acc[i][j][q] = 0.f;

    auto load_stage = [&](int ch, int s) {
        const uint32_t base = sb + (uint32_t)s * STAGE_B;
        const size_t ke = (size_t)ch * BK;
        #pragma unroll
        for (int c = 0; c < 4; ++c) {
            CP16(base + dofs[c],          gA + ke + c * 8);
            CP16(base + TILE_B + dofs[c], gB + ke + c * 8);
        }
    };

    load_stage(0, 0); CP_COMMIT();
    load_stage(1, 1); CP_COMMIT();

    #pragma unroll 1
    for (int ch = 0; ch < NCH; ++ch) {
        CP_WAIT(1);
        __syncthreads();
        if (ch + STAGES - 1 < NCH)
            load_stage(ch + STAGES - 1, (ch + STAGES - 1) % STAGES);
        CP_COMMIT();

        const uint32_t stb = sb + (uint32_t)(ch % STAGES) * STAGE_B;
        const uint32_t tA = stb, tB = stb + TILE_B;

        #pragma unroll
        for (int ks = 0; ks < 4; ++ks) {
            uint32_t a[4][4], b[2][4];
            #pragma unroll
            for (int mi = 0; mi < 4; ++mi)
                ldsm4(a[mi], saddr(tA, rA + mi * 16, ks * 2 + cA));
            #pragma unroll
            for (int ng = 0; ng < 2; ++ng)
                ldsm4(b[ng], saddr(tB, rB + ng * 16, ks * 2 + cB));
            #pragma unroll
            for (int mi = 0; mi < 4; ++mi) {
                #pragma unroll
                for (int ni = 0; ni < 4; ++ni) {
                    const int g = ni >> 1, o = (ni & 1) * 2;
                    mma16816(acc[mi][ni], a[mi], b[g][o], b[g][o + 1]);
                }
            }
        }
    }

    {
        const int g = lane >> 2, tq = lane & 3;
        #pragma unroll
        for (int mi = 0; mi < 4; ++mi) {
            const int row = m0 + (wid >> 2) * 64 + mi * 16 + g;
            #pragma unroll
            for (int ni = 0; ni < 4; ++ni) {
                const int col = n0 + (wid & 3) * 32 + ni * 8 + tq * 2;
                __half* p = g_lin + (size_t)row * NOUT + col;
                *(__half2*)p                      = __floats2half2_rn(acc[mi][ni][0], acc[mi][ni][1]);
                *(__half2*)(p + (size_t)8 * NOUT) = __floats2half2_rn(acc[mi][ni][2], acc[mi][ni][3]);
            }
        }
    }

    // ======== arrival: last CTA of this row-block runs the epilogue ========
    __shared__ int is_last;
    __threadfence();
    __syncthreads();
    if (tid == 0) {
        const int old = atomicAdd(&g_cnt[blockIdx.y], 1);
        is_last = (old == (NOUT / BN) - 1);
        if (is_last) g_cnt[blockIdx.y] = 0;   // reset for next launch (graph replay)
    }
    __syncthreads();
    if (!is_last) return;
    __threadfence();   // acquire: see all 32 CTAs' g_lin writes

    // ======== epilogue: warp-per-row, 8 warps x 16 iterations = 128 rows ========
    const float inv = 1.0f / HIDDEN;
    #pragma unroll 1
    for (int it = 0; it < BM / 8; ++it) {
        const int r = m0 + it * 8 + wid;
        const __half* rowp = g_lin + (size_t)r * NOUT;

        // pass 1: per-gate stats (streaming, L2-hot)
        float mu[4], rs[4];
        #pragma unroll
        for (int g = 0; g < 4; ++g) {
            float s = 0.f, q = 0.f;
            #pragma unroll
            for (int p = 0; p < 4; ++p) {
                float f[8];
                h8_to_f(*(const uint4*)(rowp + g * 1024 + p * 256 + lane * 8), f);
                #pragma unroll
                for (int e = 0; e < 8; ++e) { s += f[e]; q += f[e] * f[e]; }
            }
            s = wredsum(s); q = wredsum(q);
            mu[g] = s * inv;
            rs[g] = rsqrtf(q * inv - mu[g] * mu[g] + 1e-5f);
        }

        // pass 2: normalize + gates + cell update (re-read from L2)
        float cnv[4][8];
        uint32_t ogp[4][4];
        float s2 = 0.f, q2 = 0.f;
        #pragma unroll
        for (int p = 0; p < 4; ++p) {
            const int jo = p * 256 + lane * 8;   // element offset within HIDDEN
            float fi[8], ff[8], fo[8], fc[8];
            h8_to_f(*(const uint4*)(rowp +        jo), fi);
            h8_to_f(*(const uint4*)(rowp + 1024 + jo), ff);
            h8_to_f(*(const uint4*)(rowp + 2048 + jo), fo);
            h8_to_f(*(const uint4*)(rowp + 3072 + jo), fc);

            const float4* lwi = (const float4*)(lnw_h +        jo);
            const float4* lbi = (const float4*)(lnb_h +        jo);
            const float4* lwf = (const float4*)(lnw_h + 1024 + jo);
            const float4* lbf = (const float4*)(lnb_h + 1024 + jo);
            const float4* lwo = (const float4*)(lnw_h + 2048 + jo);
            const float4* lbo = (const float4*)(lnb_h + 2048 + jo);
            const float4* lwg = (const float4*)(lnw_h + 3072 + jo);
            const float4* lbg = (const float4*)(lnb_h + 3072 + jo);
            const float4* cop = (const float4*)(cin + (size_t)r * HIDDEN + jo);

            float lw[8], lb[8], w2[8], b2[8], w3[8], b3[8], w4[8], b4[8], co[8];
            *(float4*)&lw[0] = lwi[0]; *(float4*)&lw[4] = lwi[1];
            *(float4*)&lb[0] = lbi[0]; *(float4*)&lb[4] = lbi[1];
            *(float4*)&w2[0] = lwf[0]; *(float4*)&w2[4] = lwf[1];
            *(float4*)&b2[0] = lbf[0]; *(float4*)&b2[4] = lbf[1];
            *(float4*)&w3[0] = lwo[0]; *(float4*)&w3[4] = lwo[1];
            *(float4*)&b3[0] = lbo[0]; *(float4*)&b3[4] = lbo[1];
            *(float4*)&w4[0] = lwg[0]; *(float4*)&w4[4] = lwg[1];
            *(float4*)&b4[0] = lbg[0]; *(float4*)&b4[4] = lbg[1];
            *(float4*)&co[0] = cop[0]; *(float4*)&co[4] = cop[1];

            float ogf[8];
            #pragma unroll
            for (int e = 0; e < 8; ++e) {
                const float gi = (fi[e] - mu[0]) * rs[0] * lw[e] + lb[e];
                const float gf = (ff[e] - mu[1]) * rs[1] * w2[e] + b2[e];
                const float go = (fo[e] - mu[2]) * rs[2] * w3[e] + b3[e];
                const float gc = (fc[e] - mu[3]) * rs[3] * w4[e] + b4[e];
                const float cv = fsig(gf + 1.0f) * co[e] + fsig(gi) * ftanh(gc);
                cnv[p][e] = cv;
                ogf[e]    = fsig(go);
                s2 += cv;
                q2 += cv * cv;
            }
            #pragma unroll
            for (int e = 0; e < 4; ++e) {
                const __half2 hh = __floats2half2_rn(ogf[2 * e], ogf[2 * e + 1]);
                ogp[p][e] = *(const uint32_t*)&hh;
            }
        }
        s2 = wredsum(s2); q2 = wredsum(q2);
        const float mu2 = s2 * inv;
        const float rs2 = rsqrtf(q2 * inv - mu2 * mu2 + 1e-5f);

        // pass 3: cell LN + outputs
        #pragma unroll
        for (int p = 0; p < 4; ++p) {
            const int jo = p * 256 + lane * 8;
            const float4* lwc4 = (const float4*)(lnw_c + jo);
            const float4* lbc4 = (const float4*)(lnb_c + jo);
            float wc[8], bc[8];
            *(float4*)&wc[0] = lwc4[0]; *(float4*)&wc[4] = lwc4[1];
            *(float4*)&bc[0] = lbc4[0]; *(float4*)&bc[4] = lbc4[1];
            float ho[8];
            #pragma unroll
            for (int e = 0; e < 8; ++e) {
                const float2 of = __half22float2(*(const __half2*)&ogp[p][e >> 1]);
                const float o = (e & 1) ? of.y : of.x;
                ho[e] = o * ftanh((cnv[p][e] - mu2) * rs2 * wc[e] + bc[e]);
            }
            float4* hp = (float4*)(h_out + (size_t)r * HIDDEN + jo);
            float4* cp = (float4*)(c_out + (size_t)r * HIDDEN + jo);
            hp[0] = *(float4*)&ho[0];     hp[1] = *(float4*)&ho[4];
            cp[0] = *(float4*)&cnv[p][0]; cp[1] = *(float4*)&cnv[p][4];
        }
    }
}

// ---------------- launch ----------------
extern "C" void kernel_launch(void* const* d_in, const int* in_sizes, int n_in,
                              void* d_out, int out_size)
{
    const float* x     = (const float*)d_in[0];
    const float* h     = (const float*)d_in[1];
    const float* c     = (const float*)d_in[2];
    const float* wih   = (const float*)d_in[3];
    const float* whh   = (const float*)d_in[4];
    const float* lnw_h = (const float*)d_in[5];
    const float* lnb_h = (const float*)d_in[6];
    const float* lnw_c = (const float*)d_in[7];
    const float* lnb_c = (const float*)d_in[8];

    float* h_out = (float*)d_out;
    float* c_out = h_out + (size_t)BATCH * HIDDEN;

    cudaFuncSetAttribute(lnlstm_fused,
                         cudaFuncAttributeMaxDynamicSharedMemorySize, SMEM_B);

    lnlstm_convert<<<dim3((BATCH * KTOT / 4) / 256, 2), 256>>>(x, h, wih, whh);
    lnlstm_fused<<<dim3(NOUT / BN, BATCH / BM), 256, SMEM_B>>>(
        c, lnw_h, lnb_h, lnw_c, lnb_c, h_out, c_out);
}

// round 12
// speedup vs baseline: 2.7518x; 2.7518x over previous
#include <cuda_runtime.h>
#include <cuda_fp16.h>
#include <stdint.h>
#include <math.h>

#define BATCH  4096
#define HIDDEN 1024
#define INPUT  512
#define NOUT   4096
#define KTOT   1536
#define BM     128
#define BN     128
#define BK     64
#define NCH    (KTOT / BK)          // 24
#define STAGES 3
#define TILE_B (BM * BK * 2)        // 16384 B
#define STAGE_B (2 * TILE_B)        // 32768 B
#define SMEM_B  (STAGES * STAGE_B)  // 98304 B -> 2 CTAs/SM

// ---------------- device scratch ----------------
__device__ __half g_lin[(size_t)BATCH * NOUT];   // fp16 lin scratch (32 MB)
__device__ __half g_A[(size_t)BATCH * KTOT];
__device__ __half g_B[(size_t)NOUT  * KTOT];

// ---------------- helpers ----------------
__device__ __forceinline__ uint32_t smem_u32(const void* p) {
    uint32_t a;
    asm("{ .reg .u64 t; cvta.to.shared.u64 t, %1; cvt.u32.u64 %0, t; }" : "=r"(a) : "l"(p));
    return a;
}
#define CP16(dst, src) \
    asm volatile("cp.async.cg.shared.global [%0], [%1], 16;" :: "r"(dst), "l"(src) : "memory")
#define CP_COMMIT() asm volatile("cp.async.commit_group;" ::: "memory")
#define CP_WAIT(n)  asm volatile("cp.async.wait_group %0;" :: "n"(n) : "memory")

__device__ __forceinline__ void ldsm4(uint32_t* r, uint32_t addr) {
    asm volatile("ldmatrix.sync.aligned.m8n8.x4.shared.b16 {%0,%1,%2,%3}, [%4];"
                 : "=r"(r[0]), "=r"(r[1]), "=r"(r[2]), "=r"(r[3]) : "r"(addr));
}
__device__ __forceinline__ void mma16816(float* d, const uint32_t* a,
                                         uint32_t b0, uint32_t b1) {
    asm volatile("mma.sync.aligned.m16n8k16.row.col.f32.f16.f16.f32 "
                 "{%0,%1,%2,%3}, {%4,%5,%6,%7}, {%8,%9}, {%0,%1,%2,%3};"
                 : "+f"(d[0]), "+f"(d[1]), "+f"(d[2]), "+f"(d[3])
                 : "r"(a[0]), "r"(a[1]), "r"(a[2]), "r"(a[3]), "r"(b0), "r"(b1));
}
__device__ __forceinline__ uint32_t saddr(uint32_t tile, int row, int c) {
    return tile + (uint32_t)(row * 128) + ((uint32_t)((c ^ (row & 7)) << 4));
}
__device__ __forceinline__ float fsig(float x)  { return 1.0f / (1.0f + __expf(-x)); }
__device__ __forceinline__ float ftanh(float x) { return 1.0f - 2.0f / (1.0f + __expf(2.0f * x)); }
__device__ __forceinline__ void h8_to_f(uint4 u, float* f) {
    const __half2* h = (const __half2*)&u;
    float2 a;
    a = __half22float2(h[0]); f[0] = a.x; f[1] = a.y;
    a = __half22float2(h[1]); f[2] = a.x; f[3] = a.y;
    a = __half22float2(h[2]); f[4] = a.x; f[5] = a.y;
    a = __half22float2(h[3]); f[6] = a.x; f[7] = a.y;
}

// ---------------- fp16 conversion: A = [x|h], B = [wih|whh] ----------------
// grid.x in [0,6144): blocks [0,2048) -> INPUT section, [2048,6144) -> HIDDEN
// section. grid.y: 0 -> A (x,h), 1 -> B (wih,whh). No integer division.
__global__ __launch_bounds__(256)
void lnlstm_convert(const float* __restrict__ x,  const float* __restrict__ h,
                    const float* __restrict__ wi, const float* __restrict__ wh)
{
    const int blk = blockIdx.x;
    __half* dstb = blockIdx.y ? g_B : g_A;
    const float* src;
    uint32_t row, col, dcol;
    if (blk < 2048) {                                  // INPUT section (512 cols)
        const uint32_t e0 = (blk * 256u + threadIdx.x) * 4u;
        row  = e0 >> 9;
        col  = e0 & 511u;
        dcol = col;
        src  = blockIdx.y ? wi : x;
        src += (size_t)row * INPUT + col;
    } else {                                           // HIDDEN section (1024 cols)
        const uint32_t e0 = ((blk - 2048) * 256u + threadIdx.x) * 4u;
        row  = e0 >> 10;
        col  = e0 & 1023u;
        dcol = INPUT + col;
        src  = blockIdx.y ? wh : h;
        src += (size_t)row * HIDDEN + col;
    }
    const float4 v = *(const float4*)src;
    __half2 p0 = __floats2half2_rn(v.x, v.y);
    __half2 p1 = __floats2half2_rn(v.z, v.w);
    uint2 u;
    u.x = *(uint32_t*)&p0;
    u.y = *(uint32_t*)&p1;
    *(uint2*)(dstb + (size_t)row * KTOT + dcol) = u;
}

// ---------------- GEMM: g_lin = A * B^T (fp16 mma.sync, fp32 accum) ----------------
// CTA 128x128, 8 warps as 2(M) x 4(N), warp tile 64x32. 3 stages, 2 CTAs/SM.
// (byte-identical to round-9 version — at the legacy mma.sync ceiling)
__global__ void __launch_bounds__(256, 2)
lnlstm_mma_gemm()
{
    extern __shared__ char smem[];
    const uint32_t sb = smem_u32(smem);
    const int tid  = threadIdx.x;
    const int wid  = tid >> 5;
    const int lane = tid & 31;
    const int m0 = blockIdx.y * BM;
    const int n0 = blockIdx.x * BN;

    const int trow = tid >> 1;
    const int tc0  = (tid & 1) * 4;
    const __half* gA = g_A + (size_t)(m0 + trow) * KTOT + tc0 * 8;
    const __half* gB = g_B + (size_t)(n0 + trow) * KTOT + tc0 * 8;
    uint32_t dofs[4];
    #pragma unroll
    for (int c = 0; c < 4; ++c)
        dofs[c] = (uint32_t)(trow * 128) + ((uint32_t)(((tc0 + c) ^ (trow & 7)) << 4));

    const int sub = lane >> 3, r8 = lane & 7;
    const int rA  = (wid >> 2) * 64 + (sub & 1) * 8 + r8;
    const int cA  = sub >> 1;
    const int rB  = (wid & 3) * 32 + (sub >> 1) * 8 + r8;
    const int cB  = sub & 1;

    float acc[4][4][4];
    #pragma unroll
    for (int i = 0; i < 4; ++i)
        #pragma unroll
        for (int j = 0; j < 4; ++j)
            #pragma unroll
            for (int q = 0; q < 4; ++q) acc[i][j][q] = 0.f;

    auto load_stage = [&](int ch, int s) {
        const uint32_t base = sb + (uint32_t)s * STAGE_B;
        const size_t ke = (size_t)ch * BK;
        #pragma unroll
        for (int c = 0; c < 4; ++c) {
            CP16(base + dofs[c],          gA + ke + c * 8);
            CP16(base + TILE_B + dofs[c], gB + ke + c * 8);
        }
    };

    load_stage(0, 0); CP_COMMIT();
    load_stage(1, 1); CP_COMMIT();

    #pragma unroll 1
    for (int ch = 0; ch < NCH; ++ch) {
        CP_WAIT(1);
        __syncthreads();
        if (ch + STAGES - 1 < NCH)
            load_stage(ch + STAGES - 1, (ch + STAGES - 1) % STAGES);
        CP_COMMIT();

        const uint32_t stb = sb + (uint32_t)(ch % STAGES) * STAGE_B;
        const uint32_t tA = stb, tB = stb + TILE_B;

        #pragma unroll
        for (int ks = 0; ks < 4; ++ks) {
            uint32_t a[4][4], b[2][4];
            #pragma unroll
            for (int mi = 0; mi < 4; ++mi)
                ldsm4(a[mi], saddr(tA, rA + mi * 16, ks * 2 + cA));
            #pragma unroll
            for (int ng = 0; ng < 2; ++ng)
                ldsm4(b[ng], saddr(tB, rB + ng * 16, ks * 2 + cB));
            #pragma unroll
            for (int mi = 0; mi < 4; ++mi) {
                #pragma unroll
                for (int ni = 0; ni < 4; ++ni) {
                    const int g = ni >> 1, o = (ni & 1) * 2;
                    mma16816(acc[mi][ni], a[mi], b[g][o], b[g][o + 1]);
                }
            }
        }
    }

    const int g = lane >> 2, tq = lane & 3;
    #pragma unroll
    for (int mi = 0; mi < 4; ++mi) {
        const int row = m0 + (wid >> 2) * 64 + mi * 16 + g;
        #pragma unroll
        for (int ni = 0; ni < 4; ++ni) {
            const int col = n0 + (wid & 3) * 32 + ni * 8 + tq * 2;
            __half* p = g_lin + (size_t)row * NOUT + col;
            *(__half2*)p                      = __floats2half2_rn(acc[mi][ni][0], acc[mi][ni][1]);
            *(__half2*)(p + (size_t)8 * NOUT) = __floats2half2_rn(acc[mi][ni][2], acc[mi][ni][3]);
        }
    }
}

// ---------------- epilogue: 128 threads/row, 2 barriers total ----------------
__global__ __launch_bounds__(128)
void lnlstm_epilogue(const float* __restrict__ c,
                     const float* __restrict__ lnw_h, const float* __restrict__ lnb_h,
                     const float* __restrict__ lnw_c, const float* __restrict__ lnb_c,
                     float* __restrict__ h_out, float* __restrict__ c_out)
{
    __shared__ float4 redS[4], redQ[4];
    __shared__ float2 red2[4];
    const int b = blockIdx.x;
    const int t = threadIdx.x;           // 0..127
    const int w = t >> 5, l = t & 31;
    const __half* rowp = g_lin + (size_t)b * NOUT;
    const int jo = t * 8;                // element offset within a gate (0..1016)
    const float inv = 1.0f / HIDDEN;

    // load 8 elems per gate (one uint4 each), accumulate stats
    float f[4][8];
    float s[4], q[4];
    #pragma unroll
    for (int g = 0; g < 4; ++g) {
        h8_to_f(*(const uint4*)(rowp + g * HIDDEN + jo), f[g]);
        s[g] = 0.f; q[g] = 0.f;
        #pragma unroll
        for (int e = 0; e < 8; ++e) { s[g] += f[g][e]; q[g] += f[g][e] * f[g][e]; }
    }
    #pragma unroll
    for (int o = 16; o > 0; o >>= 1) {
        #pragma unroll
        for (int g = 0; g < 4; ++g) {
            s[g] += __shfl_xor_sync(0xffffffffu, s[g], o);
            q[g] += __shfl_xor_sync(0xffffffffu, q[g], o);
        }
    }
    if (l == 0) { redS[w] = make_float4(s[0], s[1], s[2], s[3]);
                  redQ[w] = make_float4(q[0], q[1], q[2], q[3]); }
    __syncthreads();
    float mu[4], rs[4];
    {
        float4 S = redS[0], Q = redQ[0];
        #pragma unroll
        for (int i = 1; i < 4; ++i) {
            const float4 a = redS[i], d = redQ[i];
            S.x += a.x; S.y += a.y; S.z += a.z; S.w += a.w;
            Q.x += d.x; Q.y += d.y; Q.z += d.z; Q.w += d.w;
        }
        mu[0] = S.x * inv; mu[1] = S.y * inv; mu[2] = S.z * inv; mu[3] = S.w * inv;
        rs[0] = rsqrtf(Q.x * inv - mu[0] * mu[0] + 1e-5f);
        rs[1] = rsqrtf(Q.y * inv - mu[1] * mu[1] + 1e-5f);
        rs[2] = rsqrtf(Q.z * inv - mu[2] * mu[2] + 1e-5f);
        rs[3] = rsqrtf(Q.w * inv - mu[3] * mu[3] + 1e-5f);
    }

    // normalize + gates + cell update
    float lw[8], lb[8], cn[8], og[8];
    float s2 = 0.f, q2 = 0.f;
    {
        float co[8];
        *(float4*)&co[0] = ((const float4*)(c + (size_t)b * HIDDEN + jo))[0];
        *(float4*)&co[4] = ((const float4*)(c + (size_t)b * HIDDEN + jo))[1];
        float gi[8], gf[8], go[8], gc[8];
        #pragma unroll
        for (int g = 0; g < 4; ++g) {
            *(float4*)&lw[0] = ((const float4*)(lnw_h + g * HIDDEN + jo))[0];
            *(float4*)&lw[4] = ((const float4*)(lnw_h + g * HIDDEN + jo))[1];
            *(float4*)&lb[0] = ((const float4*)(lnb_h + g * HIDDEN + jo))[0];
            *(float4*)&lb[4] = ((const float4*)(lnb_h + g * HIDDEN + jo))[1];
            float* out = (g == 0) ? gi : (g == 1) ? gf : (g == 2) ? go : gc;
            #pragma unroll
            for (int e = 0; e < 8; ++e)
                out[e] = (f[g][e] - mu[g]) * rs[g] * lw[e] + lb[e];
        }
        #pragma unroll
        for (int e = 0; e < 8; ++e) {
            const float cv = fsig(gf[e] + 1.0f) * co[e] + fsig(gi[e]) * ftanh(gc[e]);
            cn[e] = cv;
            og[e] = fsig(go[e]);
            s2 += cv;
            q2 += cv * cv;
        }
    }
    #pragma unroll
    for (int o = 16; o > 0; o >>= 1) {
        s2 += __shfl_xor_sync(0xffffffffu, s2, o);
        q2 += __shfl_xor_sync(0xffffffffu, q2, o);
    }
    if (l == 0) red2[w] = make_float2(s2, q2);
    __syncthreads();
    float2 P = red2[0];
    #pragma unroll
    for (int i = 1; i < 4; ++i) { P.x += red2[i].x; P.y += red2[i].y; }
    const float mu2 = P.x * inv;
    const float rs2 = rsqrtf(P.y * inv - mu2 * mu2 + 1e-5f);

    // cell LN + outputs
    *(float4*)&lw[0] = ((const float4*)(lnw_c + jo))[0];
    *(float4*)&lw[4] = ((const float4*)(lnw_c + jo))[1];
    *(float4*)&lb[0] = ((const float4*)(lnb_c + jo))[0];
    *(float4*)&lb[4] = ((const float4*)(lnb_c + jo))[1];
    float ho[8];
    #pragma unroll
    for (int e = 0; e < 8; ++e)
        ho[e] = og[e] * ftanh((cn[e] - mu2) * rs2 * lw[e] + lb[e]);
    float4* hp = (float4*)(h_out + (size_t)b * HIDDEN + jo);
    float4* cp = (float4*)(c_out + (size_t)b * HIDDEN + jo);
    hp[0] = *(float4*)&ho[0]; hp[1] = *(float4*)&ho[4];
    cp[0] = *(float4*)&cn[0]; cp[1] = *(float4*)&cn[4];
}

// ---------------- launch ----------------
extern "C" void kernel_launch(void* const* d_in, const int* in_sizes, int n_in,
                              void* d_out, int out_size)
{
    const float* x     = (const float*)d_in[0];
    const float* h     = (const float*)d_in[1];
    const float* c     = (const float*)d_in[2];
    const float* wih   = (const float*)d_in[3];
    const float* whh   = (const float*)d_in[4];
    const float* lnw_h = (const float*)d_in[5];
    const float* lnb_h = (const float*)d_in[6];
    const float* lnw_c = (const float*)d_in[7];
    const float* lnb_c = (const float*)d_in[8];

    float* h_out = (float*)d_out;
    float* c_out = h_out + (size_t)BATCH * HIDDEN;

    cudaFuncSetAttribute(lnlstm_mma_gemm,
                         cudaFuncAttributeMaxDynamicSharedMemorySize, SMEM_B);

    lnlstm_convert<<<dim3(6144, 2), 256>>>(x, h, wih, whh);
    lnlstm_mma_gemm<<<dim3(NOUT / BN, BATCH / BM), 256, SMEM_B>>>();
    lnlstm_epilogue<<<BATCH, 128>>>(c, lnw_h, lnb_h, lnw_c, lnb_c, h_out, c_out);
}